// round 14
// baseline (speedup 1.0000x reference)
#include <cuda_runtime.h>
#include <cuda_fp16.h>
#include <math.h>
#include <stdint.h>

#define TT 49
#define UNITS 256
#define QN 9
#define DIMF 256
#define BATCH 2048
#define G4 1024
#define RS (TT * UNITS)
#define PI_F 3.14159265358979f

#define S_GS 1032               // gate tile row stride (floats)
#define S_CS 260                // c-state fp32 row stride (floats)
#define S_CH 264                // c-state fp16 row stride (halves)
#define KT16 16                 // 256 / 16 k-tiles (fp16 MMA)
#define R_ROWS 32               // batch rows per CTA
#define RECUR_BLOCKS (BATCH / R_ROWS)   // 64
// gs + cs_full (floats) + cs_h (halves) = 182,272 B
#define RECUR_SMEM ((R_ROWS * S_GS + R_ROWS * S_CS) * 4 + R_ROWS * S_CH * 2)

// ---- static device scratch ----
__device__ float    g_U[(size_t)TT * UNITS * UNITS];   // [t][k][n]
__device__ float    g_Whx[(size_t)DIMF * G4];          // x-part weights, gate-interleaved cols [k][j*4+g]
__device__ uint2    g_Wbh[(size_t)KT16 * 128 * 32];    // c-part weights fp16, m16n8k16 B-fragment order
__device__ float    g_Xp[(size_t)BATCH * TT * G4];     // gate-interleaved [bt*1024 + j*4 + g]
__device__ float    g_S[(size_t)BATCH * TT * UNITS];   // [bt*256 + j]

__device__ __forceinline__ float sigf(float x) {
    return __fdividef(1.0f, 1.0f + __expf(-x));
}
__device__ __forceinline__ float tanh_fast(float x) {
    return __fdividef(2.0f, 1.0f + __expf(-2.0f * x)) - 1.0f;
}

__device__ __forceinline__ uint32_t f2tf(float x) {
    uint32_t r;
    asm("cvt.rna.tf32.f32 %0, %1;" : "=r"(r) : "f"(x));
    return r;
}

__device__ __forceinline__ void mma_tf32(float* c, const uint32_t* a, const uint32_t* b) {
    asm volatile(
        "mma.sync.aligned.m16n8k8.row.col.f32.tf32.tf32.f32 "
        "{%0,%1,%2,%3}, {%4,%5,%6,%7}, {%8,%9}, {%0,%1,%2,%3};\n"
        : "+f"(c[0]), "+f"(c[1]), "+f"(c[2]), "+f"(c[3])
        : "r"(a[0]), "r"(a[1]), "r"(a[2]), "r"(a[3]), "r"(b[0]), "r"(b[1]));
}

__device__ __forceinline__ void mma_fp16(float* c, const uint32_t* a, const uint32_t* b) {
    asm volatile(
        "mma.sync.aligned.m16n8k16.row.col.f32.f16.f16.f32 "
        "{%0,%1,%2,%3}, {%4,%5,%6,%7}, {%8,%9}, {%0,%1,%2,%3};\n"
        : "+f"(c[0]), "+f"(c[1]), "+f"(c[2]), "+f"(c[3])
        : "r"(a[0]), "r"(a[1]), "r"(a[2]), "r"(a[3]), "r"(b[0]), "r"(b[1]));
}

// ---------------------------------------------------------------------------
// U[t][k][n] = sum_q Q[k, n*9+q] * B[t][q]
// ---------------------------------------------------------------------------
__global__ void build_U(const float* __restrict__ Q) {
    int t = blockIdx.x, i = blockIdx.y, j = threadIdx.x;
    __shared__ float Bq[QN];
    if (threadIdx.x < QN) {
        int q = threadIdx.x;
        float tt = (float)t / (float)(TT - 1);
        float v;
        if (q == 0) v = 1.0f;
        else {
            int h = (q + 1) >> 1;
            float w = 2.0f * PI_F * (float)h * tt;
            v = 1.41421356237309515f * ((q & 1) ? sinf(w) : cosf(w));
        }
        Bq[q] = v;
    }
    __syncthreads();
    const float* qrow = Q + (size_t)i * (UNITS * QN) + (size_t)j * QN;
    float acc = 0.0f;
#pragma unroll
    for (int q = 0; q < QN; q++) acc = fmaf(qrow[q], Bq[q], acc);
    g_U[((size_t)t * UNITS + i) * UNITS + j] = acc;
}

// ---------------------------------------------------------------------------
// x-part weights -> gate-interleaved columns: Whx[k][j*4+g]
// ---------------------------------------------------------------------------
__global__ void prep_Whx(const float* __restrict__ Wf, const float* __restrict__ Wi,
                         const float* __restrict__ Wc, const float* __restrict__ Wo) {
    int idx = blockIdx.x * blockDim.x + threadIdx.x;
    if (idx >= 256 * UNITS) return;
    int k = idx >> 8, j = idx & 255;
    int src = (k + 256) * UNITS + j;       // x-part = rows 256..511 of cat weight
    float4 v = make_float4(Wf[src], Wi[src], Wc[src], Wo[src]);
    *(float4*)(g_Whx + (size_t)k * G4 + (size_t)j * 4) = v;
}

// ---------------------------------------------------------------------------
// c-part weights -> fp16, m16n8k16 B-fragment order.
// uint2 idx = (kt*128 + nt)*32 + lane
//   n = nt*8 + (lane>>2); k0 = kt*16 + 2*(lane&3); j = n>>2; gate = n&3
// ---------------------------------------------------------------------------
__global__ void prep_Wbh(const float* __restrict__ Wf, const float* __restrict__ Wi,
                         const float* __restrict__ Wc, const float* __restrict__ Wo) {
    int idx = blockIdx.x * blockDim.x + threadIdx.x;
    if (idx >= KT16 * 128 * 32) return;
    int lane = idx & 31;
    int nt = (idx >> 5) & 127;
    int kt = idx >> 12;
    int g = lane >> 2, tc = lane & 3;
    int n = nt * 8 + g;
    int j = n >> 2, gate = n & 3;
    int k0 = kt * 16 + 2 * tc;
    const float* W = (gate == 0) ? Wf : (gate == 1) ? Wi : (gate == 2) ? Wc : Wo;
    __half2 b0 = __floats2half2_rn(W[(size_t)k0 * UNITS + j],
                                   W[(size_t)(k0 + 1) * UNITS + j]);
    __half2 b1 = __floats2half2_rn(W[(size_t)(k0 + 8) * UNITS + j],
                                   W[(size_t)(k0 + 9) * UNITS + j]);
    uint2 o;
    o.x = *(uint32_t*)&b0;
    o.y = *(uint32_t*)&b1;
    g_Wbh[idx] = o;
}

// ---------------------------------------------------------------------------
// tf32 MMA GEMM: Xp = X(100352 x 256) @ Whx(256 x 1024); contiguous stores
// (measured 348us — unchanged)
// ---------------------------------------------------------------------------
__global__ __launch_bounds__(256) void xproj_mma(const float* __restrict__ A) {
    __shared__ uint32_t As[128][36];
    __shared__ uint32_t Bs[32][136];
    int tid = threadIdx.x;
    int bm = blockIdx.x, bn = blockIdx.y;
    int w = tid >> 5, lane = tid & 31;
    int wm = (w & 3) * 32, wn = (w >> 2) * 64;
    int g = lane >> 2, tc = lane & 3;

    const float* Ab = A + (size_t)bm * 128 * DIMF;
    const float* Bb = g_Whx + (size_t)bn * 128;

    int ar0 = tid >> 3, ac = (tid & 7) * 4;
    int br0 = tid >> 5, bc = (tid & 31) * 4;

    float c[2][8][4];
#pragma unroll
    for (int mi = 0; mi < 2; mi++)
#pragma unroll
        for (int ni = 0; ni < 8; ni++)
#pragma unroll
            for (int q = 0; q < 4; q++) c[mi][ni][q] = 0.0f;

    float4 ar[4], br[4];
#pragma unroll
    for (int i = 0; i < 4; i++) {
        ar[i] = *(const float4*)(Ab + (size_t)(ar0 + 32 * i) * DIMF + ac);
        br[i] = *(const float4*)(Bb + (size_t)(br0 + 8 * i) * G4 + bc);
    }

    for (int s = 0; s < 8; s++) {
        __syncthreads();
#pragma unroll
        for (int i = 0; i < 4; i++) {
            uint32_t* pa = &As[ar0 + 32 * i][ac];
            pa[0] = f2tf(ar[i].x); pa[1] = f2tf(ar[i].y);
            pa[2] = f2tf(ar[i].z); pa[3] = f2tf(ar[i].w);
            uint32_t* pb = &Bs[br0 + 8 * i][bc];
            pb[0] = f2tf(br[i].x); pb[1] = f2tf(br[i].y);
            pb[2] = f2tf(br[i].z); pb[3] = f2tf(br[i].w);
        }
        __syncthreads();
        if (s < 7) {
            int k0 = (s + 1) * 32;
#pragma unroll
            for (int i = 0; i < 4; i++) {
                ar[i] = *(const float4*)(Ab + (size_t)(ar0 + 32 * i) * DIMF + k0 + ac);
                br[i] = *(const float4*)(Bb + (size_t)(k0 + br0 + 8 * i) * G4 + bc);
            }
        }
#pragma unroll
        for (int kk = 0; kk < 4; kk++) {
            int k8 = kk * 8;
            uint32_t af[2][4];
#pragma unroll
            for (int mi = 0; mi < 2; mi++) {
                int r0 = wm + mi * 16 + g;
                af[mi][0] = As[r0][k8 + tc];
                af[mi][1] = As[r0 + 8][k8 + tc];
                af[mi][2] = As[r0][k8 + tc + 4];
                af[mi][3] = As[r0 + 8][k8 + tc + 4];
            }
            uint32_t bf[8][2];
#pragma unroll
            for (int ni = 0; ni < 8; ni++) {
                int nc = wn + ni * 8 + g;
                bf[ni][0] = Bs[k8 + tc][nc];
                bf[ni][1] = Bs[k8 + tc + 4][nc];
            }
#pragma unroll
            for (int mi = 0; mi < 2; mi++)
#pragma unroll
                for (int ni = 0; ni < 8; ni++)
                    mma_tf32(c[mi][ni], af[mi], bf[ni]);
        }
    }

#pragma unroll
    for (int mi = 0; mi < 2; mi++) {
#pragma unroll
        for (int ni = 0; ni < 8; ni++) {
            int row0 = bm * 128 + wm + mi * 16 + g;
            int n0 = bn * 128 + wn + ni * 8 + 2 * tc;
            *(float2*)(g_Xp + (size_t)row0 * G4 + n0) =
                make_float2(c[mi][ni][0], c[mi][ni][1]);
            *(float2*)(g_Xp + (size_t)(row0 + 8) * G4 + n0) =
                make_float2(c[mi][ni][2], c[mi][ni][3]);
        }
    }
}

// ---------------------------------------------------------------------------
// fp16 tensor-core recurrence. 64 blocks x 32 batch rows, 8 warps.
// 2 m-tiles per warp -> each weight fragment feeds 2 MMAs; chip-wide weight
// traffic halved vs 16-row version. Rolling weight prefetch hides L2 latency.
// ---------------------------------------------------------------------------
__global__ __launch_bounds__(256, 1) void recur_mma() {
    extern __shared__ float sm[];
    float*  gs      = sm;                                  // [R_ROWS][S_GS]
    float*  cs_full = sm + R_ROWS * S_GS;                  // [R_ROWS][S_CS]
    __half* cs_h    = (__half*)(cs_full + R_ROWS * S_CS);  // [R_ROWS][S_CH]

    int tid = threadIdx.x;
    int w = tid >> 5, lane = tid & 31;
    int g = lane >> 2, tc = lane & 3;
    int b0 = blockIdx.x * R_ROWS;

#pragma unroll
    for (int p = 0; p < R_ROWS; p++) {
        cs_full[p * S_CS + tid] = 0.0f;
        cs_h[p * S_CH + tid] = __float2half(0.0f);
    }
    __syncthreads();

    const uint2* __restrict__ Wbh = g_Wbh;
    const float4* __restrict__ Xp4 = (const float4*)g_Xp;

    // A-fragment smem base pointers (per-thread, constant over t)
    const __half* a00 = cs_h + (size_t)g * S_CH + 2 * tc;          // mi=0, rows g / g+8
    const __half* a01 = cs_h + (size_t)(g + 8) * S_CH + 2 * tc;
    const __half* a10 = cs_h + (size_t)(16 + g) * S_CH + 2 * tc;   // mi=1, rows 16+g / 24+g
    const __half* a11 = cs_h + (size_t)(24 + g) * S_CH + 2 * tc;

    for (int t = 0; t < TT; t++) {
        float acc[2][16][4];
#pragma unroll
        for (int mi = 0; mi < 2; mi++)
#pragma unroll
            for (int ni = 0; ni < 16; ni++)
#pragma unroll
                for (int q = 0; q < 4; q++) acc[mi][ni][q] = 0.0f;

        uint2 buf0[8], buf1[8];
#pragma unroll
        for (int i = 0; i < 8; i++)
            buf0[i] = Wbh[(size_t)(w * 16 + i) * 32 + lane];

#pragma unroll 2
        for (int kt = 0; kt < KT16; kt++) {
            int k2 = kt * 16;
            // load second n-half weights for this kt
#pragma unroll
            for (int i = 0; i < 8; i++)
                buf1[i] = Wbh[(size_t)(kt * 128 + w * 16 + 8 + i) * 32 + lane];
            // A fragments for both m-tiles
            uint32_t ah[2][4];
            ah[0][0] = *(const uint32_t*)(a00 + k2);
            ah[0][1] = *(const uint32_t*)(a01 + k2);
            ah[0][2] = *(const uint32_t*)(a00 + k2 + 8);
            ah[0][3] = *(const uint32_t*)(a01 + k2 + 8);
            ah[1][0] = *(const uint32_t*)(a10 + k2);
            ah[1][1] = *(const uint32_t*)(a11 + k2);
            ah[1][2] = *(const uint32_t*)(a10 + k2 + 8);
            ah[1][3] = *(const uint32_t*)(a11 + k2 + 8);
            // MMAs on first n-half (weights already resident)
#pragma unroll
            for (int i = 0; i < 8; i++) {
                mma_fp16(acc[0][i], ah[0], (const uint32_t*)&buf0[i]);
                mma_fp16(acc[1][i], ah[1], (const uint32_t*)&buf0[i]);
            }
            // prefetch first n-half of next kt while second half computes
            if (kt < KT16 - 1) {
#pragma unroll
                for (int i = 0; i < 8; i++)
                    buf0[i] = Wbh[(size_t)((kt + 1) * 128 + w * 16 + i) * 32 + lane];
            }
#pragma unroll
            for (int i = 0; i < 8; i++) {
                mma_fp16(acc[0][8 + i], ah[0], (const uint32_t*)&buf1[i]);
                mma_fp16(acc[1][8 + i], ah[1], (const uint32_t*)&buf1[i]);
            }
        }

        // stage gate tile to smem (n ordering = j*4 + gate)
#pragma unroll
        for (int mi = 0; mi < 2; mi++)
#pragma unroll
            for (int ni = 0; ni < 16; ni++) {
                int n0 = w * 128 + ni * 8 + 2 * tc;
                *(float2*)&gs[(size_t)(mi * 16 + g) * S_GS + n0] =
                    make_float2(acc[mi][ni][0], acc[mi][ni][1]);
                *(float2*)&gs[(size_t)(mi * 16 + g + 8) * S_GS + n0] =
                    make_float2(acc[mi][ni][2], acc[mi][ni][3]);
            }
        __syncthreads();

#pragma unroll 4
        for (int p = 0; p < R_ROWS; p++) {
            float4 gv = *(const float4*)&gs[(size_t)p * S_GS + 4 * tid];
            float4 xv = Xp4[((size_t)(b0 + p) * TT + t) * UNITS + tid];
            float f  = sigf(gv.x + xv.x);
            float i_ = sigf(gv.y + xv.y);
            float gg = sigf(gv.z + xv.z);
            float oo = tanh_fast(gv.w + xv.w);
            float cold = cs_full[p * S_CS + tid];
            float cnew = fmaf(f, cold, i_ * gg);
            cs_full[p * S_CS + tid] = cnew;
            cs_h[p * S_CH + tid] = __float2half_rn(cnew);
            g_S[((size_t)(b0 + p) * TT + t) * UNITS + tid] = oo * tanh_fast(cnew);
        }
        __syncthreads();
    }
}

// ---------------------------------------------------------------------------
// tf32 MMA: out[b,t,:] = tanh(S[b,t,:] @ U[t]); grid (16, 2, 49)
// ---------------------------------------------------------------------------
__global__ __launch_bounds__(256) void hproj_mma(float* __restrict__ out) {
    __shared__ uint32_t As[128][36];
    __shared__ uint32_t Bs[32][136];
    int tid = threadIdx.x;
    int bm = blockIdx.x, bn = blockIdx.y, t = blockIdx.z;
    int w = tid >> 5, lane = tid & 31;
    int wm = (w & 3) * 32, wn = (w >> 2) * 64;
    int g = lane >> 2, tc = lane & 3;

    const float* Ab = g_S + (size_t)bm * 128 * RS + (size_t)t * UNITS;
    const float* Bb = g_U + (size_t)t * UNITS * UNITS + (size_t)bn * 128;

    int ar0 = tid >> 3, ac = (tid & 7) * 4;
    int br0 = tid >> 5, bc = (tid & 31) * 4;

    float c[2][8][4];
#pragma unroll
    for (int mi = 0; mi < 2; mi++)
#pragma unroll
        for (int ni = 0; ni < 8; ni++)
#pragma unroll
            for (int q = 0; q < 4; q++) c[mi][ni][q] = 0.0f;

    float4 ar[4], br[4];
#pragma unroll
    for (int i = 0; i < 4; i++) {
        ar[i] = *(const float4*)(Ab + (size_t)(ar0 + 32 * i) * RS + ac);
        br[i] = *(const float4*)(Bb + (size_t)(br0 + 8 * i) * UNITS + bc);
    }

    for (int s = 0; s < 8; s++) {
        __syncthreads();
#pragma unroll
        for (int i = 0; i < 4; i++) {
            uint32_t* pa = &As[ar0 + 32 * i][ac];
            pa[0] = f2tf(ar[i].x); pa[1] = f2tf(ar[i].y);
            pa[2] = f2tf(ar[i].z); pa[3] = f2tf(ar[i].w);
            uint32_t* pb = &Bs[br0 + 8 * i][bc];
            pb[0] = f2tf(br[i].x); pb[1] = f2tf(br[i].y);
            pb[2] = f2tf(br[i].z); pb[3] = f2tf(br[i].w);
        }
        __syncthreads();
        if (s < 7) {
            int k0 = (s + 1) * 32;
#pragma unroll
            for (int i = 0; i < 4; i++) {
                ar[i] = *(const float4*)(Ab + (size_t)(ar0 + 32 * i) * RS + k0 + ac);
                br[i] = *(const float4*)(Bb + (size_t)(k0 + br0 + 8 * i) * UNITS + bc);
            }
        }
#pragma unroll
        for (int kk = 0; kk < 4; kk++) {
            int k8 = kk * 8;
            uint32_t af[2][4];
#pragma unroll
            for (int mi = 0; mi < 2; mi++) {
                int r0 = wm + mi * 16 + g;
                af[mi][0] = As[r0][k8 + tc];
                af[mi][1] = As[r0 + 8][k8 + tc];
                af[mi][2] = As[r0][k8 + tc + 4];
                af[mi][3] = As[r0 + 8][k8 + tc + 4];
            }
            uint32_t bf[8][2];
#pragma unroll
            for (int ni = 0; ni < 8; ni++) {
                int nc = wn + ni * 8 + g;
                bf[ni][0] = Bs[k8 + tc][nc];
                bf[ni][1] = Bs[k8 + tc + 4][nc];
            }
#pragma unroll
            for (int mi = 0; mi < 2; mi++)
#pragma unroll
                for (int ni = 0; ni < 8; ni++)
                    mma_tf32(c[mi][ni], af[mi], bf[ni]);
        }
    }

    float* Cb = out + (size_t)bm * 128 * RS + (size_t)t * UNITS + (size_t)bn * 128;
#pragma unroll
    for (int mi = 0; mi < 2; mi++) {
#pragma unroll
        for (int ni = 0; ni < 8; ni++) {
            int r0 = wm + mi * 16 + g;
            int col = wn + ni * 8 + 2 * tc;
            float2 v0 = make_float2(tanhf(c[mi][ni][0]), tanhf(c[mi][ni][1]));
            float2 v1 = make_float2(tanhf(c[mi][ni][2]), tanhf(c[mi][ni][3]));
            *(float2*)(Cb + (size_t)r0 * RS + col) = v0;
            *(float2*)(Cb + (size_t)(r0 + 8) * RS + col) = v1;
        }
    }
}

extern "C" void kernel_launch(void* const* d_in, const int* in_sizes, int n_in,
                              void* d_out, int out_size) {
    const float* x  = (const float*)d_in[0];
    const float* Wf = (const float*)d_in[1];
    const float* Wi = (const float*)d_in[2];
    const float* Wc = (const float*)d_in[3];
    const float* Wo = (const float*)d_in[4];
    const float* Q  = (const float*)d_in[5];
    float* out = (float*)d_out;

    cudaFuncSetAttribute(recur_mma, cudaFuncAttributeMaxDynamicSharedMemorySize, RECUR_SMEM);

    build_U<<<dim3(TT, UNITS), 256>>>(Q);
    prep_Whx<<<(256 * UNITS + 255) / 256, 256>>>(Wf, Wi, Wc, Wo);
    prep_Wbh<<<(KT16 * 128 * 32 + 255) / 256, 256>>>(Wf, Wi, Wc, Wo);
    xproj_mma<<<dim3(BATCH * TT / 128, G4 / 128), 256>>>(x);
    recur_mma<<<RECUR_BLOCKS, 256, RECUR_SMEM>>>();
    hproj_mma<<<dim3(BATCH / 128, UNITS / 128, TT), 256>>>(out);
}

// round 17
// speedup vs baseline: 2.0643x; 2.0643x over previous
#include <cuda_runtime.h>
#include <cuda_fp16.h>
#include <math.h>
#include <stdint.h>

#define TT 49
#define UNITS 256
#define QN 9
#define DIMF 256
#define BATCH 2048
#define G4 1024
#define RS (TT * UNITS)
#define PI_F 3.14159265358979f

#define S_GS 1032               // gate tile row stride (floats)
#define S_CS 260                // c-state fp32 row stride (floats)
#define S_CH 264                // c-state fp16 row stride (halves)
#define KT16 16                 // 256 / 16 k-tiles (fp16 MMA)
// gs + cs_full (floats) + cs_h (halves) = ~91 KB
#define RECUR_SMEM ((16 * S_GS + 16 * S_CS) * 4 + 16 * S_CH * 2)

// ---- static device scratch ----
__device__ float    g_U[(size_t)TT * UNITS * UNITS];   // [t][k][n]
__device__ float    g_Whx[(size_t)DIMF * G4];          // x-part weights, gate-interleaved cols [k][j*4+g]
__device__ uint2    g_Wbh[(size_t)KT16 * 128 * 32];    // c-part weights fp16, m16n8k16 B-fragment order
__device__ float    g_Xp[(size_t)BATCH * TT * G4];     // gate-interleaved [bt*1024 + j*4 + g]
__device__ float    g_S[(size_t)BATCH * TT * UNITS];   // [bt*256 + j]

__device__ __forceinline__ float sigf(float x) {
    return __fdividef(1.0f, 1.0f + __expf(-x));
}
__device__ __forceinline__ float tanh_fast(float x) {
    return __fdividef(2.0f, 1.0f + __expf(-2.0f * x)) - 1.0f;
}

__device__ __forceinline__ uint32_t f2tf(float x) {
    uint32_t r;
    asm("cvt.rna.tf32.f32 %0, %1;" : "=r"(r) : "f"(x));
    return r;
}

__device__ __forceinline__ void mma_tf32(float* c, const uint32_t* a, const uint32_t* b) {
    asm volatile(
        "mma.sync.aligned.m16n8k8.row.col.f32.tf32.tf32.f32 "
        "{%0,%1,%2,%3}, {%4,%5,%6,%7}, {%8,%9}, {%0,%1,%2,%3};\n"
        : "+f"(c[0]), "+f"(c[1]), "+f"(c[2]), "+f"(c[3])
        : "r"(a[0]), "r"(a[1]), "r"(a[2]), "r"(a[3]), "r"(b[0]), "r"(b[1]));
}

__device__ __forceinline__ void mma_fp16(float* c, const uint32_t* a, const uint32_t* b) {
    asm volatile(
        "mma.sync.aligned.m16n8k16.row.col.f32.f16.f16.f32 "
        "{%0,%1,%2,%3}, {%4,%5,%6,%7}, {%8,%9}, {%0,%1,%2,%3};\n"
        : "+f"(c[0]), "+f"(c[1]), "+f"(c[2]), "+f"(c[3])
        : "r"(a[0]), "r"(a[1]), "r"(a[2]), "r"(a[3]), "r"(b[0]), "r"(b[1]));
}

// ---------------------------------------------------------------------------
// U[t][k][n] = sum_q Q[k, n*9+q] * B[t][q]
// ---------------------------------------------------------------------------
__global__ void build_U(const float* __restrict__ Q) {
    int t = blockIdx.x, i = blockIdx.y, j = threadIdx.x;
    __shared__ float Bq[QN];
    if (threadIdx.x < QN) {
        int q = threadIdx.x;
        float tt = (float)t / (float)(TT - 1);
        float v;
        if (q == 0) v = 1.0f;
        else {
            int h = (q + 1) >> 1;
            float w = 2.0f * PI_F * (float)h * tt;
            v = 1.41421356237309515f * ((q & 1) ? sinf(w) : cosf(w));
        }
        Bq[q] = v;
    }
    __syncthreads();
    const float* qrow = Q + (size_t)i * (UNITS * QN) + (size_t)j * QN;
    float acc = 0.0f;
#pragma unroll
    for (int q = 0; q < QN; q++) acc = fmaf(qrow[q], Bq[q], acc);
    g_U[((size_t)t * UNITS + i) * UNITS + j] = acc;
}

// ---------------------------------------------------------------------------
// x-part weights -> gate-interleaved columns: Whx[k][j*4+g]
// ---------------------------------------------------------------------------
__global__ void prep_Whx(const float* __restrict__ Wf, const float* __restrict__ Wi,
                         const float* __restrict__ Wc, const float* __restrict__ Wo) {
    int idx = blockIdx.x * blockDim.x + threadIdx.x;
    if (idx >= 256 * UNITS) return;
    int k = idx >> 8, j = idx & 255;
    int src = (k + 256) * UNITS + j;       // x-part = rows 256..511 of cat weight
    float4 v = make_float4(Wf[src], Wi[src], Wc[src], Wo[src]);
    *(float4*)(g_Whx + (size_t)k * G4 + (size_t)j * 4) = v;
}

// ---------------------------------------------------------------------------
// c-part weights -> fp16, m16n8k16 B-fragment order.
// uint2 idx = (kt*128 + nt)*32 + lane
//   n = nt*8 + (lane>>2); k0 = kt*16 + 2*(lane&3); j = n>>2; gate = n&3
// ---------------------------------------------------------------------------
__global__ void prep_Wbh(const float* __restrict__ Wf, const float* __restrict__ Wi,
                         const float* __restrict__ Wc, const float* __restrict__ Wo) {
    int idx = blockIdx.x * blockDim.x + threadIdx.x;
    if (idx >= KT16 * 128 * 32) return;
    int lane = idx & 31;
    int nt = (idx >> 5) & 127;
    int kt = idx >> 12;
    int g = lane >> 2, tc = lane & 3;
    int n = nt * 8 + g;
    int j = n >> 2, gate = n & 3;
    int k0 = kt * 16 + 2 * tc;
    const float* W = (gate == 0) ? Wf : (gate == 1) ? Wi : (gate == 2) ? Wc : Wo;
    __half2 b0 = __floats2half2_rn(W[(size_t)k0 * UNITS + j],
                                   W[(size_t)(k0 + 1) * UNITS + j]);
    __half2 b1 = __floats2half2_rn(W[(size_t)(k0 + 8) * UNITS + j],
                                   W[(size_t)(k0 + 9) * UNITS + j]);
    uint2 o;
    o.x = *(uint32_t*)&b0;
    o.y = *(uint32_t*)&b1;
    g_Wbh[idx] = o;
}

// ---------------------------------------------------------------------------
// tf32 MMA GEMM: Xp = X(100352 x 256) @ Whx(256 x 1024); contiguous stores
// (measured 348us — unchanged)
// ---------------------------------------------------------------------------
__global__ __launch_bounds__(256) void xproj_mma(const float* __restrict__ A) {
    __shared__ uint32_t As[128][36];
    __shared__ uint32_t Bs[32][136];
    int tid = threadIdx.x;
    int bm = blockIdx.x, bn = blockIdx.y;
    int w = tid >> 5, lane = tid & 31;
    int wm = (w & 3) * 32, wn = (w >> 2) * 64;
    int g = lane >> 2, tc = lane & 3;

    const float* Ab = A + (size_t)bm * 128 * DIMF;
    const float* Bb = g_Whx + (size_t)bn * 128;

    int ar0 = tid >> 3, ac = (tid & 7) * 4;
    int br0 = tid >> 5, bc = (tid & 31) * 4;

    float c[2][8][4];
#pragma unroll
    for (int mi = 0; mi < 2; mi++)
#pragma unroll
        for (int ni = 0; ni < 8; ni++)
#pragma unroll
            for (int q = 0; q < 4; q++) c[mi][ni][q] = 0.0f;

    float4 ar[4], br[4];
#pragma unroll
    for (int i = 0; i < 4; i++) {
        ar[i] = *(const float4*)(Ab + (size_t)(ar0 + 32 * i) * DIMF + ac);
        br[i] = *(const float4*)(Bb + (size_t)(br0 + 8 * i) * G4 + bc);
    }

    for (int s = 0; s < 8; s++) {
        __syncthreads();
#pragma unroll
        for (int i = 0; i < 4; i++) {
            uint32_t* pa = &As[ar0 + 32 * i][ac];
            pa[0] = f2tf(ar[i].x); pa[1] = f2tf(ar[i].y);
            pa[2] = f2tf(ar[i].z); pa[3] = f2tf(ar[i].w);
            uint32_t* pb = &Bs[br0 + 8 * i][bc];
            pb[0] = f2tf(br[i].x); pb[1] = f2tf(br[i].y);
            pb[2] = f2tf(br[i].z); pb[3] = f2tf(br[i].w);
        }
        __syncthreads();
        if (s < 7) {
            int k0 = (s + 1) * 32;
#pragma unroll
            for (int i = 0; i < 4; i++) {
                ar[i] = *(const float4*)(Ab + (size_t)(ar0 + 32 * i) * DIMF + k0 + ac);
                br[i] = *(const float4*)(Bb + (size_t)(k0 + br0 + 8 * i) * G4 + bc);
            }
        }
#pragma unroll
        for (int kk = 0; kk < 4; kk++) {
            int k8 = kk * 8;
            uint32_t af[2][4];
#pragma unroll
            for (int mi = 0; mi < 2; mi++) {
                int r0 = wm + mi * 16 + g;
                af[mi][0] = As[r0][k8 + tc];
                af[mi][1] = As[r0 + 8][k8 + tc];
                af[mi][2] = As[r0][k8 + tc + 4];
                af[mi][3] = As[r0 + 8][k8 + tc + 4];
            }
            uint32_t bf[8][2];
#pragma unroll
            for (int ni = 0; ni < 8; ni++) {
                int nc = wn + ni * 8 + g;
                bf[ni][0] = Bs[k8 + tc][nc];
                bf[ni][1] = Bs[k8 + tc + 4][nc];
            }
#pragma unroll
            for (int mi = 0; mi < 2; mi++)
#pragma unroll
                for (int ni = 0; ni < 8; ni++)
                    mma_tf32(c[mi][ni], af[mi], bf[ni]);
        }
    }

#pragma unroll
    for (int mi = 0; mi < 2; mi++) {
#pragma unroll
        for (int ni = 0; ni < 8; ni++) {
            int row0 = bm * 128 + wm + mi * 16 + g;
            int n0 = bn * 128 + wn + ni * 8 + 2 * tc;
            *(float2*)(g_Xp + (size_t)row0 * G4 + n0) =
                make_float2(c[mi][ni][0], c[mi][ni][1]);
            *(float2*)(g_Xp + (size_t)(row0 + 8) * G4 + n0) =
                make_float2(c[mi][ni][2], c[mi][ni][3]);
        }
    }
}

// ---------------------------------------------------------------------------
// fp16 tensor-core recurrence. 128 blocks x 16 batch rows, 512 threads
// (16 warps: each warp 64 n-cols; each thread 8 epilogue cells).
// Xp prefetched into registers before MMA phase to hide DRAM latency.
// ---------------------------------------------------------------------------
__global__ __launch_bounds__(512, 1) void recur_mma() {
    extern __shared__ float sm[];
    float*  gs      = sm;                                  // [16][S_GS]
    float*  cs_full = sm + 16 * S_GS;                      // [16][S_CS]
    __half* cs_h    = (__half*)(cs_full + 16 * S_CS);      // [16][S_CH]

    int tid = threadIdx.x;
    int w = tid >> 5, lane = tid & 31;
    int g = lane >> 2, tc = lane & 3;
    int b0 = blockIdx.x * 16;

    // epilogue mapping: thread -> unit j, rows ep0..ep0+7
    int ej = tid & 255;
    int ep0 = (tid >> 8) * 8;

    if (tid < 256) {
#pragma unroll
        for (int p = 0; p < 16; p++) {
            cs_full[p * S_CS + tid] = 0.0f;
            cs_h[p * S_CH + tid] = __float2half(0.0f);
        }
    }
    __syncthreads();

    const uint2* __restrict__ Wbh = g_Wbh;
    const float4* __restrict__ Xp4 = (const float4*)g_Xp;

    // A-fragment smem base pointers (constant over t)
    const __half* a0 = cs_h + (size_t)g * S_CH + 2 * tc;
    const __half* a1 = cs_h + (size_t)(g + 8) * S_CH + 2 * tc;

    for (int t = 0; t < TT; t++) {
        // prefetch this step's Xp operands (consumed in epilogue, hidden by MMA)
        float4 xv[8];
#pragma unroll
        for (int i = 0; i < 8; i++)
            xv[i] = Xp4[((size_t)(b0 + ep0 + i) * TT + t) * UNITS + ej];

        float acc[8][4];
#pragma unroll
        for (int ni = 0; ni < 8; ni++)
#pragma unroll
            for (int q = 0; q < 4; q++) acc[ni][q] = 0.0f;

#pragma unroll 2
        for (int kt = 0; kt < KT16; kt++) {
            int k2 = kt * 16;
            uint2 bf[8];
#pragma unroll
            for (int ni = 0; ni < 8; ni++)
                bf[ni] = Wbh[(size_t)(kt * 128 + w * 8 + ni) * 32 + lane];
            uint32_t ah[4];
            ah[0] = *(const uint32_t*)(a0 + k2);
            ah[1] = *(const uint32_t*)(a1 + k2);
            ah[2] = *(const uint32_t*)(a0 + k2 + 8);
            ah[3] = *(const uint32_t*)(a1 + k2 + 8);
#pragma unroll
            for (int ni = 0; ni < 8; ni++)
                mma_fp16(acc[ni], ah, (const uint32_t*)&bf[ni]);
        }

        // stage gate tile to smem (n ordering = j*4 + gate)
#pragma unroll
        for (int ni = 0; ni < 8; ni++) {
            int n0 = w * 64 + ni * 8 + 2 * tc;
            *(float2*)&gs[(size_t)g * S_GS + n0]       = make_float2(acc[ni][0], acc[ni][1]);
            *(float2*)&gs[(size_t)(g + 8) * S_GS + n0] = make_float2(acc[ni][2], acc[ni][3]);
        }
        __syncthreads();

        // elementwise epilogue: 8 cells per thread (rows ep0..ep0+7, unit ej)
#pragma unroll
        for (int i = 0; i < 8; i++) {
            int p = ep0 + i;
            float4 gv = *(const float4*)&gs[(size_t)p * S_GS + 4 * ej];
            float f  = sigf(gv.x + xv[i].x);
            float i_ = sigf(gv.y + xv[i].y);
            float gg = sigf(gv.z + xv[i].z);
            float oo = tanh_fast(gv.w + xv[i].w);
            float cold = cs_full[p * S_CS + ej];
            float cnew = fmaf(f, cold, i_ * gg);
            cs_full[p * S_CS + ej] = cnew;
            cs_h[p * S_CH + ej] = __float2half_rn(cnew);
            g_S[((size_t)(b0 + p) * TT + t) * UNITS + ej] = oo * tanh_fast(cnew);
        }
        __syncthreads();
    }
}

// ---------------------------------------------------------------------------
// tf32 MMA: out[b,t,:] = tanh(S[b,t,:] @ U[t]); grid (16, 2, 49)
// ---------------------------------------------------------------------------
__global__ __launch_bounds__(256) void hproj_mma(float* __restrict__ out) {
    __shared__ uint32_t As[128][36];
    __shared__ uint32_t Bs[32][136];
    int tid = threadIdx.x;
    int bm = blockIdx.x, bn = blockIdx.y, t = blockIdx.z;
    int w = tid >> 5, lane = tid & 31;
    int wm = (w & 3) * 32, wn = (w >> 2) * 64;
    int g = lane >> 2, tc = lane & 3;

    const float* Ab = g_S + (size_t)bm * 128 * RS + (size_t)t * UNITS;
    const float* Bb = g_U + (size_t)t * UNITS * UNITS + (size_t)bn * 128;

    int ar0 = tid >> 3, ac = (tid & 7) * 4;
    int br0 = tid >> 5, bc = (tid & 31) * 4;

    float c[2][8][4];
#pragma unroll
    for (int mi = 0; mi < 2; mi++)
#pragma unroll
        for (int ni = 0; ni < 8; ni++)
#pragma unroll
            for (int q = 0; q < 4; q++) c[mi][ni][q] = 0.0f;

    float4 ar[4], br[4];
#pragma unroll
    for (int i = 0; i < 4; i++) {
        ar[i] = *(const float4*)(Ab + (size_t)(ar0 + 32 * i) * RS + ac);
        br[i] = *(const float4*)(Bb + (size_t)(br0 + 8 * i) * UNITS + bc);
    }

    for (int s = 0; s < 8; s++) {
        __syncthreads();
#pragma unroll
        for (int i = 0; i < 4; i++) {
            uint32_t* pa = &As[ar0 + 32 * i][ac];
            pa[0] = f2tf(ar[i].x); pa[1] = f2tf(ar[i].y);
            pa[2] = f2tf(ar[i].z); pa[3] = f2tf(ar[i].w);
            uint32_t* pb = &Bs[br0 + 8 * i][bc];
            pb[0] = f2tf(br[i].x); pb[1] = f2tf(br[i].y);
            pb[2] = f2tf(br[i].z); pb[3] = f2tf(br[i].w);
        }
        __syncthreads();
        if (s < 7) {
            int k0 = (s + 1) * 32;
#pragma unroll
            for (int i = 0; i < 4; i++) {
                ar[i] = *(const float4*)(Ab + (size_t)(ar0 + 32 * i) * RS + k0 + ac);
                br[i] = *(const float4*)(Bb + (size_t)(k0 + br0 + 8 * i) * UNITS + bc);
            }
        }
#pragma unroll
        for (int kk = 0; kk < 4; kk++) {
            int k8 = kk * 8;
            uint32_t af[2][4];
#pragma unroll
            for (int mi = 0; mi < 2; mi++) {
                int r0 = wm + mi * 16 + g;
                af[mi][0] = As[r0][k8 + tc];
                af[mi][1] = As[r0 + 8][k8 + tc];
                af[mi][2] = As[r0][k8 + tc + 4];
                af[mi][3] = As[r0 + 8][k8 + tc + 4];
            }
            uint32_t bf[8][2];
#pragma unroll
            for (int ni = 0; ni < 8; ni++) {
                int nc = wn + ni * 8 + g;
                bf[ni][0] = Bs[k8 + tc][nc];
                bf[ni][1] = Bs[k8 + tc + 4][nc];
            }
#pragma unroll
            for (int mi = 0; mi < 2; mi++)
#pragma unroll
                for (int ni = 0; ni < 8; ni++)
                    mma_tf32(c[mi][ni], af[mi], bf[ni]);
        }
    }

    float* Cb = out + (size_t)bm * 128 * RS + (size_t)t * UNITS + (size_t)bn * 128;
#pragma unroll
    for (int mi = 0; mi < 2; mi++) {
#pragma unroll
        for (int ni = 0; ni < 8; ni++) {
            int r0 = wm + mi * 16 + g;
            int col = wn + ni * 8 + 2 * tc;
            float2 v0 = make_float2(tanhf(c[mi][ni][0]), tanhf(c[mi][ni][1]));
            float2 v1 = make_float2(tanhf(c[mi][ni][2]), tanhf(c[mi][ni][3]));
            *(float2*)(Cb + (size_t)r0 * RS + col) = v0;
            *(float2*)(Cb + (size_t)(r0 + 8) * RS + col) = v1;
        }
    }
}

extern "C" void kernel_launch(void* const* d_in, const int* in_sizes, int n_in,
                              void* d_out, int out_size) {
    const float* x  = (const float*)d_in[0];
    const float* Wf = (const float*)d_in[1];
    const float* Wi = (const float*)d_in[2];
    const float* Wc = (const float*)d_in[3];
    const float* Wo = (const float*)d_in[4];
    const float* Q  = (const float*)d_in[5];
    float* out = (float*)d_out;

    cudaFuncSetAttribute(recur_mma, cudaFuncAttributeMaxDynamicSharedMemorySize, RECUR_SMEM);

    build_U<<<dim3(TT, UNITS), 256>>>(Q);
    prep_Whx<<<(256 * UNITS + 255) / 256, 256>>>(Wf, Wi, Wc, Wo);
    prep_Wbh<<<(KT16 * 128 * 32 + 255) / 256, 256>>>(Wf, Wi, Wc, Wo);
    xproj_mma<<<dim3(BATCH * TT / 128, G4 / 128), 256>>>(x);
    recur_mma<<<BATCH / 16, 512, RECUR_SMEM>>>();
    hproj_mma<<<dim3(BATCH / 128, UNITS / 128, TT), 256>>>(out);
}